// round 10
// baseline (speedup 1.0000x reference)
#include <cuda_runtime.h>
#include <cstdint>

// Water constraint residuals:
//   x: [B=16, N=200000, D=18] fp32; l: [3] fp32
//   out: [B, N, 3] fp32 = |r0-r1|-l0, |r1-r2|-l1, |r2-r0|-l2
//
// Persistent double-buffered pipeline. Per 4-row group (288B) the needed
// bytes are [0,256) = 16 float4s. Tile = 64 groups = 256 rows = 1024 float4s,
// staged via cp.async.cg (coalesced, L1-bypass, same 8-of-9 sector DRAM
// footprint). Two smem stages: while computing tile i, tile i+1 is in
// flight — DRAM request queue never drains within a block, and persistent
// blocks (888 total) eliminate CTA-churn gaps.

#define GROUPS_PER_TILE 64
#define GF4             17                    // 16 data float4 + 1 pad
#define TILE_F4         (GROUPS_PER_TILE * GF4)   // 1088 float4 / stage
#define GROUP_F         (GF4 * 4)             // 68 words

__device__ __forceinline__ void prefetch_tile(
    const float4* __restrict__ x4, long long tile, uint32_t s_stage, int tid)
{
    long long g_base = tile * GROUPS_PER_TILE;
    #pragma unroll
    for (int i = 0; i < 4; i++) {
        int L = tid + 256 * i;
        int gl = L >> 4;          // local group 0..63
        int j  = L & 15;          // float4 within group
        const float4* src = x4 + (g_base + gl) * 18 + j;
        uint32_t dst = s_stage + (uint32_t)(gl * GF4 + j) * 16;
        asm volatile("cp.async.cg.shared.global [%0], [%1], 16;"
                     :: "r"(dst), "l"(src));
    }
    asm volatile("cp.async.commit_group;");
}

__global__ __launch_bounds__(256) void water_kernel5(
    const float4* __restrict__ x4,
    const float* __restrict__ l,
    float* __restrict__ out,
    int num_tiles)
{
    __shared__ float4 sm4[2 * TILE_F4];
    float* smf = reinterpret_cast<float*>(sm4);

    const int tid = threadIdx.x;
    const uint32_t s_base = (uint32_t)__cvta_generic_to_shared(sm4);

    const float l0 = __ldg(l + 0);
    const float l1 = __ldg(l + 1);
    const float l2 = __ldg(l + 2);

    long long tile = blockIdx.x;
    const long long stride = gridDim.x;

    if (tile < num_tiles)
        prefetch_tile(x4, tile, s_base, tid);     // stage 0

    for (int it = 0; tile < num_tiles; it++, tile += stride) {
        const int cur = it & 1;
        const bool more = (tile + stride) < num_tiles;

        if (more)
            prefetch_tile(x4, tile + stride, s_base + (cur ^ 1) * (TILE_F4 * 16), tid);

        if (more) asm volatile("cp.async.wait_group 1;");
        else      asm volatile("cp.async.wait_group 0;");
        __syncthreads();

        // ---- Compute: thread t -> row (t&3) of local group (t>>2) ----
        const float* sm = smf + cur * (TILE_F4 * 4);
        const int base = (tid >> 2) * GROUP_F + (tid & 3) * 18;   // even
        const float2* s2 = reinterpret_cast<const float2*>(sm + base);
        float2 p01 = s2[0];        // f0 f1
        float2 p23 = s2[1];        // f2 f3
        float2 p45 = s2[2];        // f4 f5
        float2 p67 = s2[3];        // f6 f7
        float  f8  = sm[base + 8];

        // r0=(f0,f1,f2) r1=(f3,f4,f5) r2=(f6,f7,f8)
        float d0x = p01.x - p23.y, d0y = p01.y - p45.x, d0z = p23.x - p45.y;
        float d1x = p23.y - p67.x, d1y = p45.x - p67.y, d1z = p45.y - f8;
        float d2x = p67.x - p01.x, d2y = p67.y - p01.y, d2z = f8 - p23.x;

        float n0 = sqrtf(fmaf(d0x, d0x, fmaf(d0y, d0y, d0z * d0z)));
        float n1 = sqrtf(fmaf(d1x, d1x, fmaf(d1y, d1y, d1z * d1z)));
        float n2 = sqrtf(fmaf(d2x, d2x, fmaf(d2y, d2y, d2z * d2z)));

        float* o = out + (tile * 256 + tid) * 3;
        __stcs(o + 0, n0 - l0);
        __stcs(o + 1, n1 - l1);
        __stcs(o + 2, n2 - l2);

        __syncthreads();           // smem reads done before next prefetch reuses cur
    }
}

extern "C" void kernel_launch(void* const* d_in, const int* in_sizes, int n_in,
                              void* d_out, int out_size)
{
    const float4* x4 = (const float4*)d_in[0];
    const float* l = (const float*)d_in[1];
    float* out = (float*)d_out;

    int M = in_sizes[0] / 18;              // 3,200,000 rows
    int num_tiles = M / 256;               // 12500 tiles of 256 rows

    int grid = 148 * 6;                    // persistent: 6 CTAs/SM (smem-limited)
    if (grid > num_tiles) grid = num_tiles;

    water_kernel5<<<grid, 256>>>(x4, l, out, num_tiles);
}

// round 11
// speedup vs baseline: 1.2970x; 1.2970x over previous
#include <cuda_runtime.h>

// Water constraint residuals:
//   x: [B=16, N=200000, D=18] fp32  (first 9 floats/row = 3 particles x xyz)
//   l: [3] fp32; out: [B, N, 3] fp32 = |r0-r1|-l0, |r1-r2|-l1, |r2-r0|-l2
//
// Warp-autonomous staged gather (R8 structure, block barrier removed).
// Per 4-row group (288B) all needed bytes live in [0,256) = 16 float4s.
// Each warp owns 8 groups (32 rows): 4 coalesced LDG.128/lane stage
// 8x256B into its private smem slice, __syncwarp only, then each lane
// computes one row. Warps never couple -> no barrier spread, smoother
// DRAM request stream. Identical 8-of-9 sector DRAM footprint.

#define GF4      17                 // 16 data float4 + 1 pad per group
#define GROUP_F  (GF4 * 4)          // 68 words

__global__ __launch_bounds__(256) void water_kernel6(
    const float4* __restrict__ x4,
    const float* __restrict__ l,
    float* __restrict__ out)
{
    __shared__ float4 sm4[64 * GF4];            // 64 groups (8 per warp)
    float* sm = reinterpret_cast<float*>(sm4);

    const int tid  = threadIdx.x;
    const int w    = tid >> 5;                  // warp 0..7
    const int lane = tid & 31;

    // Block covers 64 groups = 256 rows; warp w owns groups [8w, 8w+8).
    const long long g_blk = (long long)blockIdx.x * 64;

    // ---- Warp-local stage: 8 groups x 16 float4 = 128 float4, 4/lane ----
    #pragma unroll
    for (int i = 0; i < 4; i++) {
        int L  = lane + 32 * i;                 // 0..127
        int gl = L >> 4;                        // local group 0..7
        int j  = L & 15;                        // float4 within group
        float4 v = __ldcs(x4 + (g_blk + w * 8 + gl) * 18 + j);
        sm4[(w * 8 + gl) * GF4 + j] = v;
    }
    __syncwarp();

    const float l0 = __ldg(l + 0);
    const float l1 = __ldg(l + 1);
    const float l2 = __ldg(l + 2);

    // ---- Compute: lane -> row (lane&3) of local group (lane>>2) ----
    const int base = (w * 8 + (lane >> 2)) * GROUP_F + (lane & 3) * 18; // even
    const float2* s2 = reinterpret_cast<const float2*>(sm + base);
    float2 p01 = s2[0];            // f0 f1
    float2 p23 = s2[1];            // f2 f3
    float2 p45 = s2[2];            // f4 f5
    float2 p67 = s2[3];            // f6 f7
    float  f8  = sm[base + 8];

    // r0=(f0,f1,f2) r1=(f3,f4,f5) r2=(f6,f7,f8)
    float d0x = p01.x - p23.y, d0y = p01.y - p45.x, d0z = p23.x - p45.y;
    float d1x = p23.y - p67.x, d1y = p45.x - p67.y, d1z = p45.y - f8;
    float d2x = p67.x - p01.x, d2y = p67.y - p01.y, d2z = f8 - p23.x;

    float n0 = sqrtf(fmaf(d0x, d0x, fmaf(d0y, d0y, d0z * d0z)));
    float n1 = sqrtf(fmaf(d1x, d1x, fmaf(d1y, d1y, d1z * d1z)));
    float n2 = sqrtf(fmaf(d2x, d2x, fmaf(d2y, d2y, d2z * d2z)));

    // Warp writes 32 consecutive rows -> 384B contiguous.
    long long row = g_blk * 4 + w * 32 + lane;
    float* o = out + row * 3;
    __stcs(o + 0, n0 - l0);
    __stcs(o + 1, n1 - l1);
    __stcs(o + 2, n2 - l2);
}

extern "C" void kernel_launch(void* const* d_in, const int* in_sizes, int n_in,
                              void* d_out, int out_size)
{
    const float4* x4 = (const float4*)d_in[0];
    const float* l = (const float*)d_in[1];
    float* out = (float*)d_out;

    int M = in_sizes[0] / 18;      // 3,200,000 rows (divisible by 256)
    int grid = M / 256;            // 12500 blocks, 256 rows each

    water_kernel6<<<grid, 256>>>(x4, l, out);
}